// round 14
// baseline (speedup 1.0000x reference)
#include <cuda_runtime.h>

#define TPB  128
#define NGPB 8        // groups (of 32 inputs) per block
#define CPT  2        // output columns per thread
#define NGY  32       // main-path grid.y; blockIdx.y == NGY runs the const path

typedef unsigned long long ull;

// 34 pieces per group, natural order. KOFF = x index, KSCALE chosen so
// (masked field value after magic-subtract) * (x[KOFF]*KSCALE) == q * x exactly.
__constant__ int KOFF3[34] = {
    0,1,2,3,4,5,6,          // Am: r0 direct fields j0..j6
    7,8,9,10,               // As: r0>>12 fields j7..j9 + w10lo
    10,11,12,13,14,15,16,17,// Cm: w10hi + r1 direct j11..j17
    18,19,20,21,            // Cs: r1>>12 fields j18..j20 + w21lo
    21,22,23,24,25,26,27,28,// Em: w21hi + r2 direct j22..j28
    29,30,31                // Es: r2>>12 fields j29..j31
};
__constant__ float KSCALE3[34] = {
    0x1p0f, 0x1p-3f, 0x1p-6f, 0x1p-9f, 0x1p-12f, 0x1p-15f, 0x1p-18f,
    0x1p-9f, 0x1p-12f, 0x1p-15f, 0x1p-18f,
    4.0f, 0x1p-1f, 0x1p-4f, 0x1p-7f, 0x1p-10f, 0x1p-13f, 0x1p-16f, 0x1p-19f,
    0x1p-10f, 0x1p-13f, 0x1p-16f, 0x1p-19f,
    2.0f, 0x1p-2f, 0x1p-5f, 0x1p-8f, 0x1p-11f, 0x1p-14f, 0x1p-17f, 0x1p-20f,
    0x1p-11f, 0x1p-14f, 0x1p-17f
};

#define MAGD 0x4B0000004B000000ull   // fp32 2^23 exponent in both halves

// One piece for BOTH columns: 64-bit AND keeps magic+field in each half
// (2 LOP3 w/ immediates), exact packed subtract of 2^23, packed fma.
// Lanes of every f32x2 = the two output columns.
#define PP(acc, w, m, cpv) do {                                               \
    ull _t = (w) & ((((ull)((m) | 0x4B000000u)) << 32) | ((m) | 0x4B000000u));\
    asm("add.rn.f32x2 %0, %0, %1;" : "+l"(_t) : "l"(NEG64));                  \
    asm("fma.rn.f32x2 %0, %1, %2, %0;" : "+l"(acc) : "l"(_t), "l"(cpv));      \
} while (0)

// Single fused launch. blockIdx.y < NGY: quantized-GEMV K-chunk (8 groups, ring-4
// weight prefetch, cross-column packed pieces). blockIdx.y == NGY: const path.
// out must be zeroed before launch (cudaMemsetAsync).
__global__ __launch_bounds__(TPB, 8)
void k_fused(const float* __restrict__ x,
             const int*   __restrict__ qw,
             const float* __restrict__ scales,
             const float* __restrict__ zeros,
             const float* __restrict__ bias,
             const float* __restrict__ oweight,
             const int*   __restrict__ outlieridx,
             float* __restrict__ out,
             int OUTF, int INF, int NOUT)
{
    __shared__ __align__(16) float cs[NGPB * 68];
    __shared__ float wred[TPB / 32];
    __shared__ float xo[64];

    const int tid = threadIdx.x;
    const int colbase = blockIdx.x * (TPB * CPT) + tid * CPT;
    const int o0 = colbase, o1 = colbase + 1;

    if (blockIdx.y == NGY) {
        // ---- const-only path ----
        float s = 0.f;
        const float4* x4 = (const float4*)x;
        for (int i = tid; i < INF / 4; i += TPB) {
            float4 v = x4[i];
            s += (v.x + v.y) + (v.z + v.w);
        }
        #pragma unroll
        for (int d = 16; d > 0; d >>= 1) s += __shfl_xor_sync(0xFFFFFFFFu, s, d);
        if ((tid & 31) == 0) wred[tid >> 5] = s;
        if (tid < NOUT) xo[tid] = x[outlieridx[tid]];
        __syncthreads();

        const float sumx = wred[0] + wred[1] + wred[2] + wred[3];
        float base0 = bias[o0] - zeros[o0] * sumx;
        float base1 = bias[o1] - zeros[o1] * sumx;
        const float4* ow0 = (const float4*)(oweight + (size_t)o0 * NOUT);
        const float4* ow1 = (const float4*)(oweight + (size_t)o1 * NOUT);
        #pragma unroll 8
        for (int j = 0; j < NOUT / 4; ++j) {
            float4 u = ow0[j];
            float4 v = ow1[j];
            float q0 = xo[4 * j + 0], q1 = xo[4 * j + 1];
            float q2 = xo[4 * j + 2], q3 = xo[4 * j + 3];
            base0 = fmaf(u.x, q0, base0);
            base1 = fmaf(v.x, q0, base1);
            base0 = fmaf(u.y, q1, base0);
            base1 = fmaf(v.y, q1, base1);
            base0 = fmaf(u.z, q2, base0);
            base1 = fmaf(v.z, q2, base1);
            base0 = fmaf(u.w, q3, base0);
            base1 = fmaf(v.w, q3, base1);
        }
        atomicAdd(&out[o0], base0);
        atomicAdd(&out[o1], base1);
        return;
    }

    // ---- main path ----
    const int gbase = blockIdx.y * NGPB;
    const long stride = OUTF / 2;  // ull stride between qweight rows

    // Column-pair pointer: each ull load = {col0, col1} of one packed row.
    const ull* colptr = (const ull*)qw + (long)gbase * 3 * stride + (colbase >> 1);

    // Rolling ring: preload groups 0..3 (MLP=12 up front, refilled as we go).
    ull rw[4][3];
    #pragma unroll
    for (int g = 0; g < 4; ++g) {
        #pragma unroll
        for (int r = 0; r < 3; ++r)
            rw[g][r] = colptr[(3 * g + r) * stride];
    }

    // Build coefficient table: 34 pieces per group, each DUPLICATED {c, c}.
    for (int idx = tid; idx < NGPB * 68; idx += TPB) {
        int g = idx / 68, k2 = idx - g * 68, piece = k2 >> 1;
        cs[idx] = x[(gbase + g) * 32 + KOFF3[piece]] * KSCALE3[piece];
    }
    __syncthreads();

    const ull NEG64 = 0xCB000000CB000000ull;  // packed {-2^23, -2^23}

    ull a0 = 0ull, a1 = 0ull, a2 = 0ull, a3 = 0ull;

    #pragma unroll
    for (int g = 0; g < NGPB; ++g) {
        ull A = rw[g & 3][0], C = rw[g & 3][1], E = rw[g & 3][2];

        if (g + 4 < NGPB) {
            #pragma unroll
            for (int r = 0; r < 3; ++r)
                rw[g & 3][r] = colptr[(3 * (g + 4) + r) * stride];
        }

        // Per-half magic-biased words: direct (bits 0-22) and >>12 (bits 12-31).
        // 64-bit >>12 contaminates lo's top bits with hi's low bits; the
        // 0x000FFFFF mask removes them, keeping exactly (half >> 12) bits 0-19.
        ull Am = (A & 0x007FFFFF007FFFFFull) | MAGD;
        ull As = ((A >> 12) & 0x000FFFFF000FFFFFull) | MAGD;
        ull Cm = (C & 0x007FFFFF007FFFFFull) | MAGD;
        ull Cs = ((C >> 12) & 0x000FFFFF000FFFFFull) | MAGD;
        ull Em = (E & 0x007FFFFF007FFFFFull) | MAGD;
        ull Es = ((E >> 12) & 0x000FFFFF000FFFFFull) | MAGD;

        const ulonglong2* cq = (const ulonglong2*)&cs[g * 68];
        ulonglong2 v;
        v = cq[0];  PP(a0, Am, 0x00000007u, v.x);  PP(a1, Am, 0x00000038u, v.y);
        v = cq[1];  PP(a2, Am, 0x000001C0u, v.x);  PP(a3, Am, 0x00000E00u, v.y);
        v = cq[2];  PP(a0, Am, 0x00007000u, v.x);  PP(a1, Am, 0x00038000u, v.y);
        v = cq[3];  PP(a2, Am, 0x001C0000u, v.x);  PP(a3, As, 0x00000E00u, v.y);
        v = cq[4];  PP(a0, As, 0x00007000u, v.x);  PP(a1, As, 0x00038000u, v.y);
        v = cq[5];  PP(a2, As, 0x000C0000u, v.x);  PP(a3, Cm, 0x00000001u, v.y);
        v = cq[6];  PP(a0, Cm, 0x0000000Eu, v.x);  PP(a1, Cm, 0x00000070u, v.y);
        v = cq[7];  PP(a2, Cm, 0x00000380u, v.x);  PP(a3, Cm, 0x00001C00u, v.y);
        v = cq[8];  PP(a0, Cm, 0x0000E000u, v.x);  PP(a1, Cm, 0x00070000u, v.y);
        v = cq[9];  PP(a2, Cm, 0x00380000u, v.x);  PP(a3, Cs, 0x00001C00u, v.y);
        v = cq[10]; PP(a0, Cs, 0x0000E000u, v.x);  PP(a1, Cs, 0x00070000u, v.y);
        v = cq[11]; PP(a2, Cs, 0x00080000u, v.x);  PP(a3, Em, 0x00000003u, v.y);
        v = cq[12]; PP(a0, Em, 0x0000001Cu, v.x);  PP(a1, Em, 0x000000E0u, v.y);
        v = cq[13]; PP(a2, Em, 0x00000700u, v.x);  PP(a3, Em, 0x00003800u, v.y);
        v = cq[14]; PP(a0, Em, 0x0001C000u, v.x);  PP(a1, Em, 0x000E0000u, v.y);
        v = cq[15]; PP(a2, Em, 0x00700000u, v.x);  PP(a3, Es, 0x00003800u, v.y);
        v = cq[16]; PP(a0, Es, 0x0001C000u, v.x);  PP(a1, Es, 0x000E0000u, v.y);
    }

    // lo halves = column o0, hi halves = column o1.
    {
        float s0 = (__uint_as_float((unsigned)a0) + __uint_as_float((unsigned)a1)) +
                   (__uint_as_float((unsigned)a2) + __uint_as_float((unsigned)a3));
        atomicAdd(&out[o0], scales[o0] * s0);
    }
    {
        float s1 = (__uint_as_float((unsigned)(a0 >> 32)) + __uint_as_float((unsigned)(a1 >> 32))) +
                   (__uint_as_float((unsigned)(a2 >> 32)) + __uint_as_float((unsigned)(a3 >> 32)));
        atomicAdd(&out[o1], scales[o1] * s1);
    }
}

extern "C" void kernel_launch(void* const* d_in, const int* in_sizes, int n_in,
                              void* d_out, int out_size)
{
    const float* x      = (const float*)d_in[0];
    const int*   qw     = (const int*)  d_in[1];
    const float* scales = (const float*)d_in[2];
    const float* zeros  = (const float*)d_in[3];
    const float* bias   = (const float*)d_in[4];
    const float* ow     = (const float*)d_in[5];
    const int*   oidx   = (const int*)  d_in[6];
    float* out = (float*)d_out;

    const int INF  = in_sizes[0];          // 8192
    const int OUTF = in_sizes[2];          // 8192
    const int NOUT = in_sizes[6];          // 64

    cudaMemsetAsync(out, 0, (size_t)out_size * sizeof(float));

    dim3 grid(OUTF / (TPB * CPT), NGY + 1);  // (32, 33): 1024 main + 32 const blocks
    k_fused<<<grid, TPB>>>(x, qw, scales, zeros, bias, ow, oidx, out,
                           OUTF, INF, NOUT);
}

// round 15
// speedup vs baseline: 1.1026x; 1.1026x over previous
#include <cuda_runtime.h>

#define TPB  128
#define NGPB 8        // groups (of 32 inputs) per block
#define CPT  2        // output columns per thread
#define NGY  32       // main-path grid.y; blockIdx.y == NGY runs the const path

typedef unsigned long long ull;

// 34 coefficient entries per group, stored in PAIR order (2p, 2p+1 form the f32x2
// pair for piece-pair p). Piece value (masked bits, after magic-subtract) ==
// q * 2^s exactly; coeff = x[off] * KSCALE2 so fma gives q*x exactly.
__constant__ int KOFF2[34] = {
    0,1,  2,3,  4,5,  6,16,  7,8,  9,10,  10,11,  12,13,  14,15,
    17,18,  19,20,  21,31,  21,22,  23,24,  25,26,  27,28,  29,30
};
__constant__ float KSCALE2[34] = {
    0x1p0f, 0x1p-3f,   0x1p-6f, 0x1p-9f,   0x1p-12f, 0x1p-15f,
    0x1p-18f, 0x1p-16f,  // mixed pair M1: A-field j6 (bit18), C-field j16 (bit16)
    0x1p-9f, 0x1p-12f,   0x1p-15f, 0x1p-18f,   // A>>12 fields (orig bits 21,24,27,30)
    4.0f, 0x1p-1f,       0x1p-4f, 0x1p-7f,   0x1p-10f, 0x1p-13f,
    0x1p-7f, 0x1p-10f,   0x1p-13f, 0x1p-16f,    // C>>12 fields (orig 19,22,25,28)
    0x1p-19f, 0x1p-17f,  // mixed pair M2: w21lo (C bit31>>12), E-field j31 (bit29>>12)
    2.0f, 0x1p-2f,       0x1p-5f, 0x1p-8f,   0x1p-11f, 0x1p-14f,
    0x1p-17f, 0x1p-20f,  0x1p-11f, 0x1p-14f     // E direct tail + E>>12 fields
};

// 64-bit mask with the fp32 magic exponent (2^23) kept in both halves.
#define MK64(mlo, mhi) ((((ull)((mhi) | 0x4B000000u)) << 32) | (ull)((mlo) | 0x4B000000u))

// One piece-pair: 64-bit AND isolates two magic-biased fields directly into an
// aligned register pair (2 LOP3, no MOV), exact packed subtract of 2^23, packed fma.
#define PPAIR(acc, word, mlo, mhi, cpv) do {                                  \
    ull _t = (word) & MK64(mlo, mhi);                                         \
    asm("add.rn.f32x2 %0, %0, %1;" : "+l"(_t) : "l"(NEG64));                  \
    asm("fma.rn.f32x2 %0, %1, %2, %0;" : "+l"(acc) : "l"(_t), "l"(cpv));      \
} while (0)

// One 32-input group for ONE column: 17 piece-pairs into 2 packed accumulators.
__device__ __forceinline__ void docol(ull& aa, ull& ab,
                                      unsigned A, unsigned C, unsigned E,
                                      const ull (&c)[17], ull NEG64)
{
    // magic-biased direct words (fields ending <= bit 22) and >>12 shifted words
    unsigned Am = (A & 0x007FFFFFu) | 0x4B000000u;
    unsigned As = ((A >> 12) & 0x000FFFFFu) | 0x4B000000u;
    unsigned Cm = (C & 0x007FFFFFu) | 0x4B000000u;
    unsigned Cs = ((C >> 12) & 0x000FFFFFu) | 0x4B000000u;
    unsigned Em = (E & 0x007FFFFFu) | 0x4B000000u;
    unsigned Es = ((E >> 12) & 0x000FFFFFu) | 0x4B000000u;

    ull AmW = ((ull)Am << 32) | Am;
    ull AsW = ((ull)As << 32) | As;
    ull CmW = ((ull)Cm << 32) | Cm;
    ull CsW = ((ull)Cs << 32) | Cs;
    ull EmW = ((ull)Em << 32) | Em;
    ull EsW = ((ull)Es << 32) | Es;
    ull X1  = ((ull)Cm << 32) | Am;   // mixed: odd A piece + odd C piece
    ull X2  = ((ull)Es << 32) | Cs;   // mixed: w21lo + odd E piece

    PPAIR(aa, AmW, 0x00000007u, 0x00000038u, c[0]);   // j0, j1
    PPAIR(ab, AmW, 0x000001C0u, 0x00000E00u, c[1]);   // j2, j3
    PPAIR(aa, AmW, 0x00007000u, 0x00038000u, c[2]);   // j4, j5
    PPAIR(ab, X1,  0x001C0000u, 0x00070000u, c[3]);   // j6, j16
    PPAIR(aa, AsW, 0x00000E00u, 0x00007000u, c[4]);   // j7(21>>12), j8(24>>12)
    PPAIR(ab, AsW, 0x00038000u, 0x000C0000u, c[5]);   // j9(27>>12), w10lo(30>>12)
    PPAIR(aa, CmW, 0x00000001u, 0x0000000Eu, c[6]);   // w10hi, j11
    PPAIR(ab, CmW, 0x00000070u, 0x00000380u, c[7]);   // j12, j13
    PPAIR(aa, CmW, 0x00001C00u, 0x0000E000u, c[8]);   // j14, j15
    PPAIR(ab, CsW, 0x00000380u, 0x00001C00u, c[9]);   // j17(19>>12), j18(22>>12)
    PPAIR(aa, CsW, 0x0000E000u, 0x00070000u, c[10]);  // j19(25>>12), j20(28>>12)
    PPAIR(ab, X2,  0x00080000u, 0x000E0000u, c[11]);  // w21lo(31>>12), j31(29>>12)
    PPAIR(aa, EmW, 0x00000003u, 0x0000001Cu, c[12]);  // w21hi, j22
    PPAIR(ab, EmW, 0x000000E0u, 0x00000700u, c[13]);  // j23, j24
    PPAIR(aa, EmW, 0x00003800u, 0x0001C000u, c[14]);  // j25, j26
    PPAIR(ab, EmW, 0x000E0000u, 0x00700000u, c[15]);  // j27, j28
    PPAIR(aa, EsW, 0x00003800u, 0x0001C000u, c[16]);  // j29(23>>12), j30(26>>12)
}

// Single fused launch. blockIdx.y < NGY: quantized-GEMV K-chunk (8 groups, ring-4
// weight prefetch, coefficient loads as 8xLDS.128 + 1xLDS.64 to relieve the MIO
// LDS port). blockIdx.y == NGY: const path. out pre-zeroed.
__global__ __launch_bounds__(TPB, 8)
void k_fused(const float* __restrict__ x,
             const int*   __restrict__ qw,
             const float* __restrict__ scales,
             const float* __restrict__ zeros,
             const float* __restrict__ bias,
             const float* __restrict__ oweight,
             const int*   __restrict__ outlieridx,
             float* __restrict__ out,
             int OUTF, int INF, int NOUT)
{
    __shared__ __align__(16) float cs[NGPB * 36];
    __shared__ float wred[TPB / 32];
    __shared__ float xo[64];

    const int tid = threadIdx.x;
    const int colbase = blockIdx.x * (TPB * CPT) + tid * CPT;
    const int o0 = colbase, o1 = colbase + 1;

    if (blockIdx.y == NGY) {
        // ---- const-only path ----
        float s = 0.f;
        const float4* x4 = (const float4*)x;
        for (int i = tid; i < INF / 4; i += TPB) {
            float4 v = x4[i];
            s += (v.x + v.y) + (v.z + v.w);
        }
        #pragma unroll
        for (int d = 16; d > 0; d >>= 1) s += __shfl_xor_sync(0xFFFFFFFFu, s, d);
        if ((tid & 31) == 0) wred[tid >> 5] = s;
        if (tid < NOUT) xo[tid] = x[outlieridx[tid]];
        __syncthreads();

        const float sumx = wred[0] + wred[1] + wred[2] + wred[3];
        float base0 = bias[o0] - zeros[o0] * sumx;
        float base1 = bias[o1] - zeros[o1] * sumx;
        const float4* ow0 = (const float4*)(oweight + (size_t)o0 * NOUT);
        const float4* ow1 = (const float4*)(oweight + (size_t)o1 * NOUT);
        #pragma unroll 8
        for (int j = 0; j < NOUT / 4; ++j) {
            float4 u = ow0[j];
            float4 v = ow1[j];
            float q0 = xo[4 * j + 0], q1 = xo[4 * j + 1];
            float q2 = xo[4 * j + 2], q3 = xo[4 * j + 3];
            base0 = fmaf(u.x, q0, base0);
            base1 = fmaf(v.x, q0, base1);
            base0 = fmaf(u.y, q1, base0);
            base1 = fmaf(v.y, q1, base1);
            base0 = fmaf(u.z, q2, base0);
            base1 = fmaf(v.z, q2, base1);
            base0 = fmaf(u.w, q3, base0);
            base1 = fmaf(v.w, q3, base1);
        }
        atomicAdd(&out[o0], base0);
        atomicAdd(&out[o1], base1);
        return;
    }

    // ---- main path (R9 structure; vectorized coefficient loads) ----
    const int gbase = blockIdx.y * NGPB;
    const long stride = OUTF / 2;  // ull stride between qweight rows

    // Column-pair pointer: each ull load = {col0, col1} of one packed row.
    const ull* colptr = (const ull*)qw + (long)gbase * 3 * stride + (colbase >> 1);

    // Rolling ring: preload groups 0..3 (MLP=12 up front, refilled as we go).
    ull rw[4][3];
    #pragma unroll
    for (int g = 0; g < 4; ++g) {
        #pragma unroll
        for (int r = 0; r < 3; ++r)
            rw[g][r] = colptr[(3 * g + r) * stride];
    }

    // Build prescaled coefficient table (34 entries per group, pair order).
    for (int idx = tid; idx < NGPB * 34; idx += TPB) {
        int g = idx / 34, k = idx - g * 34;
        cs[g * 36 + k] = x[(gbase + g) * 32 + KOFF2[k]] * KSCALE2[k];
    }
    __syncthreads();

    const ull NEG64 = 0xCB000000CB000000ull;  // packed {-2^23, -2^23}

    ull a00 = 0ull, a01 = 0ull, a10 = 0ull, a11 = 0ull;

    #pragma unroll
    for (int g = 0; g < NGPB; ++g) {
        ull A = rw[g & 3][0], C = rw[g & 3][1], E = rw[g & 3][2];

        if (g + 4 < NGPB) {
            #pragma unroll
            for (int r = 0; r < 3; ++r)
                rw[g & 3][r] = colptr[(3 * (g + 4) + r) * stride];
        }

        // Hoist this group's 17 coefficient pairs: 8 x LDS.128 + 1 x LDS.64
        // (pieces are pair-ordered; each 16B vector = two aligned 64-bit pairs).
        ull c[17];
        {
            const ulonglong2* cq = (const ulonglong2*)&cs[g * 36];
            #pragma unroll
            for (int k = 0; k < 8; ++k) {
                ulonglong2 v = cq[k];
                c[2 * k]     = v.x;
                c[2 * k + 1] = v.y;
            }
            c[16] = *(const ull*)&cs[g * 36 + 32];
        }

        docol(a00, a01, (unsigned)A, (unsigned)C, (unsigned)E, c, NEG64);
        docol(a10, a11, (unsigned)(A >> 32), (unsigned)(C >> 32), (unsigned)(E >> 32),
              c, NEG64);
    }

    {
        float s0 = __uint_as_float((unsigned)a00) + __uint_as_float((unsigned)(a00 >> 32));
        float s1 = __uint_as_float((unsigned)a01) + __uint_as_float((unsigned)(a01 >> 32));
        atomicAdd(&out[o0], scales[o0] * (s0 + s1));
    }
    {
        float s0 = __uint_as_float((unsigned)a10) + __uint_as_float((unsigned)(a10 >> 32));
        float s1 = __uint_as_float((unsigned)a11) + __uint_as_float((unsigned)(a11 >> 32));
        atomicAdd(&out[o1], scales[o1] * (s0 + s1));
    }
}

extern "C" void kernel_launch(void* const* d_in, const int* in_sizes, int n_in,
                              void* d_out, int out_size)
{
    const float* x      = (const float*)d_in[0];
    const int*   qw     = (const int*)  d_in[1];
    const float* scales = (const float*)d_in[2];
    const float* zeros  = (const float*)d_in[3];
    const float* bias   = (const float*)d_in[4];
    const float* ow     = (const float*)d_in[5];
    const int*   oidx   = (const int*)  d_in[6];
    float* out = (float*)d_out;

    const int INF  = in_sizes[0];          // 8192
    const int OUTF = in_sizes[2];          // 8192
    const int NOUT = in_sizes[6];          // 64

    cudaMemsetAsync(out, 0, (size_t)out_size * sizeof(float));

    dim3 grid(OUTF / (TPB * CPT), NGY + 1);  // (32, 33): 1024 main + 32 const blocks
    k_fused<<<grid, TPB>>>(x, qw, scales, zeros, bias, ow, oidx, out,
                           OUTF, INF, NOUT);
}

// round 16
// speedup vs baseline: 1.2521x; 1.1356x over previous
#include <cuda_runtime.h>

#define TPB  128
#define NGPB 8        // groups (of 32 inputs) per block
#define CPT  2        // output columns per thread
#define NGY  32       // main-path grid.y; blockIdx.y == NGY runs the const path

typedef unsigned long long ull;

// 34 coefficient entries per group, stored in PAIR order (2p, 2p+1 form the f32x2
// pair for piece-pair p). Piece value (masked bits, after magic-subtract) ==
// q * 2^s exactly; coeff = x[off] * KSCALE2 so fma gives q*x exactly.
__device__ const int KOFF2[34] = {
    0,1,  2,3,  4,5,  6,16,  7,8,  9,10,  10,11,  12,13,  14,15,
    17,18,  19,20,  21,31,  21,22,  23,24,  25,26,  27,28,  29,30
};
__device__ const float KSCALE2[34] = {
    0x1p0f, 0x1p-3f,   0x1p-6f, 0x1p-9f,   0x1p-12f, 0x1p-15f,
    0x1p-18f, 0x1p-16f,  // mixed pair M1: A-field j6 (bit18), C-field j16 (bit16)
    0x1p-9f, 0x1p-12f,   0x1p-15f, 0x1p-18f,   // A>>12 fields (orig bits 21,24,27,30)
    4.0f, 0x1p-1f,       0x1p-4f, 0x1p-7f,   0x1p-10f, 0x1p-13f,
    0x1p-7f, 0x1p-10f,   0x1p-13f, 0x1p-16f,    // C>>12 fields (orig 19,22,25,28)
    0x1p-19f, 0x1p-17f,  // mixed pair M2: w21lo (C bit31>>12), E-field j31 (bit29>>12)
    2.0f, 0x1p-2f,       0x1p-5f, 0x1p-8f,   0x1p-11f, 0x1p-14f,
    0x1p-17f, 0x1p-20f,  0x1p-11f, 0x1p-14f     // E direct tail + E>>12 fields
};

// 64-bit mask with the fp32 magic exponent (2^23) kept in both halves.
#define MK64(mlo, mhi) ((((ull)((mhi) | 0x4B000000u)) << 32) | (ull)((mlo) | 0x4B000000u))

// One piece-pair: 64-bit AND isolates two magic-biased fields directly into an
// aligned register pair (2 LOP3, no MOV), exact packed subtract of 2^23, packed fma.
#define PPAIR(acc, word, mlo, mhi, cpv) do {                                  \
    ull _t = (word) & MK64(mlo, mhi);                                         \
    asm("add.rn.f32x2 %0, %0, %1;" : "+l"(_t) : "l"(NEG64));                  \
    asm("fma.rn.f32x2 %0, %1, %2, %0;" : "+l"(acc) : "l"(_t), "l"(cpv));      \
} while (0)

// One 32-input group for ONE column: 17 piece-pairs into 2 packed accumulators.
__device__ __forceinline__ void docol(ull& aa, ull& ab,
                                      unsigned A, unsigned C, unsigned E,
                                      const ull (&c)[17], ull NEG64)
{
    // magic-biased direct words (fields ending <= bit 22) and >>12 shifted words
    unsigned Am = (A & 0x007FFFFFu) | 0x4B000000u;
    unsigned As = ((A >> 12) & 0x000FFFFFu) | 0x4B000000u;
    unsigned Cm = (C & 0x007FFFFFu) | 0x4B000000u;
    unsigned Cs = ((C >> 12) & 0x000FFFFFu) | 0x4B000000u;
    unsigned Em = (E & 0x007FFFFFu) | 0x4B000000u;
    unsigned Es = ((E >> 12) & 0x000FFFFFu) | 0x4B000000u;

    ull AmW = ((ull)Am << 32) | Am;
    ull AsW = ((ull)As << 32) | As;
    ull CmW = ((ull)Cm << 32) | Cm;
    ull CsW = ((ull)Cs << 32) | Cs;
    ull EmW = ((ull)Em << 32) | Em;
    ull EsW = ((ull)Es << 32) | Es;
    ull X1  = ((ull)Cm << 32) | Am;   // mixed: odd A piece + odd C piece
    ull X2  = ((ull)Es << 32) | Cs;   // mixed: w21lo + odd E piece

    PPAIR(aa, AmW, 0x00000007u, 0x00000038u, c[0]);   // j0, j1
    PPAIR(ab, AmW, 0x000001C0u, 0x00000E00u, c[1]);   // j2, j3
    PPAIR(aa, AmW, 0x00007000u, 0x00038000u, c[2]);   // j4, j5
    PPAIR(ab, X1,  0x001C0000u, 0x00070000u, c[3]);   // j6, j16
    PPAIR(aa, AsW, 0x00000E00u, 0x00007000u, c[4]);   // j7(21>>12), j8(24>>12)
    PPAIR(ab, AsW, 0x00038000u, 0x000C0000u, c[5]);   // j9(27>>12), w10lo(30>>12)
    PPAIR(aa, CmW, 0x00000001u, 0x0000000Eu, c[6]);   // w10hi, j11
    PPAIR(ab, CmW, 0x00000070u, 0x00000380u, c[7]);   // j12, j13
    PPAIR(aa, CmW, 0x00001C00u, 0x0000E000u, c[8]);   // j14, j15
    PPAIR(ab, CsW, 0x00000380u, 0x00001C00u, c[9]);   // j17(19>>12), j18(22>>12)
    PPAIR(aa, CsW, 0x0000E000u, 0x00070000u, c[10]);  // j19(25>>12), j20(28>>12)
    PPAIR(ab, X2,  0x00080000u, 0x000E0000u, c[11]);  // w21lo(31>>12), j31(29>>12)
    PPAIR(aa, EmW, 0x00000003u, 0x0000001Cu, c[12]);  // w21hi, j22
    PPAIR(ab, EmW, 0x000000E0u, 0x00000700u, c[13]);  // j23, j24
    PPAIR(aa, EmW, 0x00003800u, 0x0001C000u, c[14]);  // j25, j26
    PPAIR(ab, EmW, 0x000E0000u, 0x00700000u, c[15]);  // j27, j28
    PPAIR(aa, EsW, 0x00003800u, 0x0001C000u, c[16]);  // j29(23>>12), j30(26>>12)
}

// Single fused launch. blockIdx.y < NGY: quantized-GEMV K-chunk (8 groups, rolling
// 4-group weight prefetch). blockIdx.y == NGY: const path. out pre-zeroed.
__global__ __launch_bounds__(TPB, 8)
void k_fused(const float* __restrict__ x,
             const int*   __restrict__ qw,
             const float* __restrict__ scales,
             const float* __restrict__ zeros,
             const float* __restrict__ bias,
             const float* __restrict__ oweight,
             const int*   __restrict__ outlieridx,
             float* __restrict__ out,
             int OUTF, int INF, int NOUT)
{
    __shared__ __align__(16) float cs[NGPB * 36];
    __shared__ float wred[TPB / 32];
    __shared__ float xo[64];

    const int tid = threadIdx.x;
    const int colbase = blockIdx.x * (TPB * CPT) + tid * CPT;
    const int o0 = colbase, o1 = colbase + 1;

    if (blockIdx.y == NGY) {
        // ---- const-only path ----
        float s = 0.f;
        const float4* x4 = (const float4*)x;
        for (int i = tid; i < INF / 4; i += TPB) {
            float4 v = x4[i];
            s += (v.x + v.y) + (v.z + v.w);
        }
        #pragma unroll
        for (int d = 16; d > 0; d >>= 1) s += __shfl_xor_sync(0xFFFFFFFFu, s, d);
        if ((tid & 31) == 0) wred[tid >> 5] = s;
        if (tid < NOUT) xo[tid] = x[outlieridx[tid]];
        __syncthreads();

        const float sumx = wred[0] + wred[1] + wred[2] + wred[3];
        float base0 = bias[o0] - zeros[o0] * sumx;
        float base1 = bias[o1] - zeros[o1] * sumx;
        const float4* ow0 = (const float4*)(oweight + (size_t)o0 * NOUT);
        const float4* ow1 = (const float4*)(oweight + (size_t)o1 * NOUT);
        #pragma unroll 8
        for (int j = 0; j < NOUT / 4; ++j) {
            float4 u = ow0[j];
            float4 v = ow1[j];
            float q0 = xo[4 * j + 0], q1 = xo[4 * j + 1];
            float q2 = xo[4 * j + 2], q3 = xo[4 * j + 3];
            base0 = fmaf(u.x, q0, base0);
            base1 = fmaf(v.x, q0, base1);
            base0 = fmaf(u.y, q1, base0);
            base1 = fmaf(v.y, q1, base1);
            base0 = fmaf(u.z, q2, base0);
            base1 = fmaf(v.z, q2, base1);
            base0 = fmaf(u.w, q3, base0);
            base1 = fmaf(v.w, q3, base1);
        }
        atomicAdd(&out[o0], base0);
        atomicAdd(&out[o1], base1);
        return;
    }

    // ---- main path ----
    const int gbase = blockIdx.y * NGPB;
    const long stride = OUTF / 2;  // ull stride between qweight rows

    // Column-pair pointer: each ull load = {col0, col1} of one packed row.
    const ull* colptr = (const ull*)qw + (long)gbase * 3 * stride + (colbase >> 1);

    // Rolling ring: preload groups 0..3 (MLP=12 up front, refilled as we go).
    ull rw[4][3];
    #pragma unroll
    for (int g = 0; g < 4; ++g) {
        #pragma unroll
        for (int r = 0; r < 3; ++r)
            rw[g][r] = colptr[(3 * g + r) * stride];
    }

    // Build prescaled coefficient table (34 entries per group, pair order).
    for (int idx = tid; idx < NGPB * 34; idx += TPB) {
        int g = idx / 34, k = idx - g * 34;
        cs[g * 36 + k] = x[(gbase + g) * 32 + KOFF2[k]] * KSCALE2[k];
    }
    __syncthreads();

    const ull NEG64 = 0xCB000000CB000000ull;  // packed {-2^23, -2^23}

    ull a00 = 0ull, a01 = 0ull, a10 = 0ull, a11 = 0ull;

    #pragma unroll
    for (int g = 0; g < NGPB; ++g) {
        ull A = rw[g & 3][0], C = rw[g & 3][1], E = rw[g & 3][2];

        if (g + 4 < NGPB) {
            #pragma unroll
            for (int r = 0; r < 3; ++r)
                rw[g & 3][r] = colptr[(3 * (g + 4) + r) * stride];
        }

        // hoist this group's 17 coefficient pairs into registers
        ull c[17];
        const ull* cp = (const ull*)&cs[g * 36];
        #pragma unroll
        for (int k = 0; k < 17; ++k) c[k] = cp[k];

        docol(a00, a01, (unsigned)A, (unsigned)C, (unsigned)E, c, NEG64);
        docol(a10, a11, (unsigned)(A >> 32), (unsigned)(C >> 32), (unsigned)(E >> 32),
              c, NEG64);
    }

    {
        float s0 = __uint_as_float((unsigned)a00) + __uint_as_float((unsigned)(a00 >> 32));
        float s1 = __uint_as_float((unsigned)a01) + __uint_as_float((unsigned)(a01 >> 32));
        atomicAdd(&out[o0], scales[o0] * (s0 + s1));
    }
    {
        float s0 = __uint_as_float((unsigned)a10) + __uint_as_float((unsigned)(a10 >> 32));
        float s1 = __uint_as_float((unsigned)a11) + __uint_as_float((unsigned)(a11 >> 32));
        atomicAdd(&out[o1], scales[o1] * (s0 + s1));
    }
}

extern "C" void kernel_launch(void* const* d_in, const int* in_sizes, int n_in,
                              void* d_out, int out_size)
{
    const float* x      = (const float*)d_in[0];
    const int*   qw     = (const int*)  d_in[1];
    const float* scales = (const float*)d_in[2];
    const float* zeros  = (const float*)d_in[3];
    const float* bias   = (const float*)d_in[4];
    const float* ow     = (const float*)d_in[5];
    const int*   oidx   = (const int*)  d_in[6];
    float* out = (float*)d_out;

    const int INF  = in_sizes[0];          // 8192
    const int OUTF = in_sizes[2];          // 8192
    const int NOUT = in_sizes[6];          // 64

    cudaMemsetAsync(out, 0, (size_t)out_size * sizeof(float));

    dim3 grid(OUTF / (TPB * CPT), NGY + 1);  // (32, 33): 1024 main + 32 const blocks
    k_fused<<<grid, TPB>>>(x, qw, scales, zeros, bias, ow, oidx, out,
                           OUTF, INF, NOUT);
}